// round 1
// baseline (speedup 1.0000x reference)
#include <cuda_runtime.h>
#include <cuda_bf16.h>

// Problem constants (shapes fixed by the dataset; B taken from in_sizes at launch)
#define C_CAND 64          // candidates per b
#define S_SYM  12          // symmetry ops
#define NC      4          // candidates per thread
#define TPB   256
#define GROUPS_PER_BLOCK (TPB / (C_CAND / NC))   // 256 / 16 = 16 b's per block
#define EPS 1e-6f

__global__ void geo_init_out(float* out) { out[0] = 0.0f; }

__global__ __launch_bounds__(TPB)
void geo_loss_kernel(const float* __restrict__ R_pred,
                     const float* __restrict__ R_gt,
                     const float* __restrict__ rot,
                     float* __restrict__ out,
                     int B, float invB)
{
    __shared__ float srot[S_SYM * 9];
    __shared__ float ssum;

    const int tid = threadIdx.x;
    if (tid < S_SYM * 9) srot[tid] = rot[tid];
    if (tid == 0) ssum = 0.0f;
    __syncthreads();

    const int b  = blockIdx.x * GROUPS_PER_BLOCK + (tid >> 4);
    const int c0 = (tid & 15) * NC;

    float cmax = -4.0f;   // running max of trace over this thread's candidates

    if (b < B) {
        // R_gt[b] : g[k*3 + j]
        float g[9];
        const float* gp = R_gt + (size_t)b * 9;
        #pragma unroll
        for (int k = 0; k < 9; k++) g[k] = __ldg(gp + k);

        // 4 candidates * 9 floats = 36 floats = 144 bytes, 16B-aligned -> 9x LDG.128
        float rp[NC * 9];
        const float4* p = reinterpret_cast<const float4*>(
            R_pred + ((size_t)b * C_CAND + c0) * 9);
        #pragma unroll
        for (int k = 0; k < 9; k++) {
            float4 v = __ldg(p + k);
            rp[4*k+0] = v.x; rp[4*k+1] = v.y; rp[4*k+2] = v.z; rp[4*k+3] = v.w;
        }

        // M[c][i*3+k] = sum_j R_pred[c,i,j] * R_gt[k,j]   (R_pred @ R_gt^T)
        float M[NC * 9];
        #pragma unroll
        for (int c = 0; c < NC; c++) {
            #pragma unroll
            for (int i = 0; i < 3; i++) {
                #pragma unroll
                for (int k = 0; k < 3; k++) {
                    float acc = rp[c*9 + i*3 + 0] * g[k*3 + 0];
                    acc = fmaf(rp[c*9 + i*3 + 1], g[k*3 + 1], acc);
                    acc = fmaf(rp[c*9 + i*3 + 2], g[k*3 + 2], acc);
                    M[c*9 + i*3 + k] = acc;
                }
            }
        }

        // tr[c,s] = <rot[s], M[c]>   (rot flattened i*3+k row-major, matches M)
        #pragma unroll
        for (int s = 0; s < S_SYM; s++) {
            float rs[9];
            #pragma unroll
            for (int e = 0; e < 9; e++) rs[e] = srot[s*9 + e];  // warp-uniform broadcast
            #pragma unroll
            for (int c = 0; c < NC; c++) {
                float t = rs[0] * M[c*9 + 0];
                #pragma unroll
                for (int e = 1; e < 9; e++) t = fmaf(rs[e], M[c*9 + e], t);
                cmax = fmaxf(cmax, t);
            }
        }
    }

    // max over the 16 lanes that share this b (xor masks 8..1 stay inside 16-lane halves)
    #pragma unroll
    for (int m = 8; m >= 1; m >>= 1)
        cmax = fmaxf(cmax, __shfl_xor_sync(0xFFFFFFFFu, cmax, m));

    if ((tid & 15) == 0 && b < B) {
        // min over (c,s) of acos(clip((tr-1)/2)) == acos(clip((max tr - 1)/2))
        float cosv = (cmax - 1.0f) * 0.5f;
        cosv = fminf(fmaxf(cosv, -1.0f + EPS), 1.0f - EPS);
        atomicAdd(&ssum, acosf(cosv) * invB);
    }
    __syncthreads();
    if (tid == 0) atomicAdd(out, ssum);   // one global atomic per block (2048 total)
}

extern "C" void kernel_launch(void* const* d_in, const int* in_sizes, int n_in,
                              void* d_out, int out_size)
{
    const float* R_pred = (const float*)d_in[0];
    const float* R_gt   = (const float*)d_in[1];
    const float* rot    = (const float*)d_in[2];
    float* out = (float*)d_out;

    const int B = in_sizes[1] / 9;   // R_gt is (B,3,3)

    geo_init_out<<<1, 1>>>(out);
    const int grid = (B + GROUPS_PER_BLOCK - 1) / GROUPS_PER_BLOCK;
    geo_loss_kernel<<<grid, TPB>>>(R_pred, R_gt, rot, out, B, 1.0f / (float)B);
}